// round 15
// baseline (speedup 1.0000x reference)
#include <cuda_runtime.h>
#include <cuda_fp16.h>
#include <math.h>
#include <stdint.h>

// ---------------------------------------------------------------------------
// RetentiveNetwork forward — FP16 mma.sync (m16n8k16) TN GEMMs, fp32 accum.
// L=2, H=2048, HEADS=8, HEAD=256, FF=8192, B=4, S=1024.
// R15: R14 + per-warp kk rotation (warps 4-7 start at kk=2) to anti-phase the
// LDSM and MMA bursts of warps sharing an SMSP (smem port / tensor overlap).
// ---------------------------------------------------------------------------

constexpr int LAYERS = 2;
constexpr int Hdim   = 2048;
constexpr int NH     = 8;
constexpr int HD     = 256;
constexpr int FFdim  = 8192;
constexpr int Bn     = 4;
constexpr int Sn     = 1024;
constexpr int MT     = Bn * Sn;

// ---------------- scratch ---------------------------------------------------
__device__ __half g_xn [MT * Hdim];
__device__ __half g_q  [MT * Hdim];
__device__ __half g_k  [MT * Hdim];
__device__ __half g_vT [MT * Hdim];     // [b][channel][s]
__device__ __half g_gt [MT * Hdim];
__device__ __half g_z  [MT * Hdim];
__device__ __half g_sc [(size_t)Bn * NH * Sn * Sn];
__device__ __half g_ffn[(size_t)MT * FFdim];
__device__ float  g_y  [MT * Hdim];
__device__ float  g_ret[MT * Hdim];
__device__ float  g_x1 [MT * Hdim];
constexpr size_t M4   = (size_t)4  * 1024 * 1024;
constexpr size_t M16  = (size_t)16 * 1024 * 1024;
constexpr size_t WT_L = (size_t)52 * 1024 * 1024;
__device__ __half g_wt[(size_t)LAYERS * WT_L];

// ---------------- helpers ---------------------------------------------------
__device__ __forceinline__ float blockReduce(float v, float* sh) {
    int lane = threadIdx.x & 31, w = threadIdx.x >> 5;
    #pragma unroll
    for (int o = 16; o; o >>= 1) v += __shfl_xor_sync(0xffffffffu, v, o);
    if (lane == 0) sh[w] = v;
    __syncthreads();
    if (w == 0) {
        float r = (lane < (int)(blockDim.x >> 5)) ? sh[lane] : 0.f;
        #pragma unroll
        for (int o = 4; o; o >>= 1) r += __shfl_xor_sync(0xffffffffu, r, o);
        if (lane == 0) sh[0] = r;
    }
    __syncthreads();
    float res = sh[0];
    __syncthreads();
    return res;
}

__device__ __forceinline__ void mma_f16(float* c, const uint32_t* a, const uint32_t* b) {
    asm volatile(
        "mma.sync.aligned.m16n8k16.row.col.f32.f16.f16.f32 "
        "{%0,%1,%2,%3}, {%4,%5,%6,%7}, {%8,%9}, {%0,%1,%2,%3};"
        : "+f"(c[0]), "+f"(c[1]), "+f"(c[2]), "+f"(c[3])
        : "r"(a[0]), "r"(a[1]), "r"(a[2]), "r"(a[3]), "r"(b[0]), "r"(b[1]));
}

__device__ __forceinline__ void ldsm4(uint32_t* r, uint32_t addr) {
    asm volatile("ldmatrix.sync.aligned.m8n8.x4.shared.b16 {%0,%1,%2,%3}, [%4];"
        : "=r"(r[0]), "=r"(r[1]), "=r"(r[2]), "=r"(r[3]) : "r"(addr));
}

__device__ __forceinline__ void cp16(uint32_t dst, const void* src) {
    asm volatile("cp.async.cg.shared.global [%0], [%1], 16;" :: "r"(dst), "l"(src));
}

// ---------------- LayerNorm (float in -> fp16 out) --------------------------
__global__ void ln_k(const float* __restrict__ x, const float* __restrict__ g,
                     const float* __restrict__ b, __half* __restrict__ o) {
    __shared__ float sh[8];
    int tok = blockIdx.x;
    const float* xp = x + (size_t)tok * Hdim;
    __half* op = o + (size_t)tok * Hdim;
    int t = threadIdx.x;
    float v[8];
    float s = 0.f;
    #pragma unroll
    for (int i = 0; i < 8; i++) { v[i] = xp[t + 256 * i]; s += v[i]; }
    float mu = blockReduce(s, sh) * (1.f / Hdim);
    float ss = 0.f;
    #pragma unroll
    for (int i = 0; i < 8; i++) { float d = v[i] - mu; ss += d * d; }
    float var = blockReduce(ss, sh) * (1.f / Hdim);
    float rs = rsqrtf(var + 1e-5f);
    #pragma unroll
    for (int i = 0; i < 8; i++) {
        int c = t + 256 * i;
        op[c] = __float2half_rn((v[i] - mu) * rs * g[c] + b[c]);
    }
}

// ---------------- GroupNorm + SiLU gate (float y, fp16 gate -> fp16) --------
__global__ void gn_gate_k(const float* __restrict__ y, const __half* __restrict__ gate,
                          const float* __restrict__ gg, const float* __restrict__ gb,
                          __half* __restrict__ z) {
    __shared__ float sh[8];
    int grp = blockIdx.x;
    int h = grp & (NH - 1);
    size_t base = (size_t)(grp >> 3) * Hdim + (size_t)h * HD;
    int t = threadIdx.x;
    float val = y[base + t];
    float mu = blockReduce(val, sh) * (1.f / HD);
    float d = val - mu;
    float var = blockReduce(d * d, sh) * (1.f / HD);
    float rs = rsqrtf(var + 1e-5f);
    int c = h * HD + t;
    float gv = __half2float(gate[base + t]);
    float silu = gv / (1.f + expf(-gv));
    z[base + t] = __float2half_rn((d * rs * gg[c] + gb[c]) * silu);
}

// ---------------- weight transpose + fp16 convert (2 launches) --------------
__global__ void wt_hh_k(const float* __restrict__ Wq, const float* __restrict__ Wk,
                        const float* __restrict__ Wv, const float* __restrict__ Wg,
                        const float* __restrict__ Wo, __half* __restrict__ wt) {
    __shared__ float tile[32][33];
    int z = blockIdx.z;
    int layer = z / 5, widx = z % 5;
    const float* W;
    switch (widx) {
        case 0: W = Wq; break;
        case 1: W = Wk; break;
        case 2: W = Wv; break;
        case 3: W = Wg; break;
        default: W = Wo; break;
    }
    W += (size_t)layer * Hdim * Hdim;
    __half* WT = wt + (size_t)layer * WT_L + (size_t)widx * M4;
    int tx = threadIdx.x & 31, ty = threadIdx.x >> 5;
    int k0 = blockIdx.y * 32, n0 = blockIdx.x * 32;
    #pragma unroll
    for (int j = 0; j < 32; j += 8)
        tile[ty + j][tx] = W[(size_t)(k0 + ty + j) * Hdim + n0 + tx];
    __syncthreads();
    #pragma unroll
    for (int j = 0; j < 32; j += 8)
        WT[(size_t)(n0 + ty + j) * Hdim + k0 + tx] = __float2half_rn(tile[tx][ty + j]);
}

__global__ void wt_ffall_k(const float* __restrict__ W1, const float* __restrict__ W2,
                           __half* __restrict__ wt) {
    __shared__ float tile[32][33];
    int z = blockIdx.z;
    int layer = z >> 1, which = z & 1;
    int K = which ? FFdim : Hdim;
    int N = which ? Hdim : FFdim;
    const float* Ws = which ? (W2 + (size_t)layer * FFdim * Hdim)
                            : (W1 + (size_t)layer * Hdim * FFdim);
    __half* WT = wt + (size_t)layer * WT_L + 5 * M4 + (which ? M16 : 0);
    int k0 = blockIdx.y * 32, n0 = blockIdx.x * 32;
    if (k0 >= K || n0 >= N) return;
    int tx = threadIdx.x & 31, ty = threadIdx.x >> 5;
    #pragma unroll
    for (int j = 0; j < 32; j += 8)
        tile[ty + j][tx] = Ws[(size_t)(k0 + ty + j) * N + n0 + tx];
    __syncthreads();
    #pragma unroll
    for (int j = 0; j < 32; j += 8)
        WT[(size_t)(n0 + ty + j) * K + k0 + tx] = __float2half_rn(tile[tx][ty + j]);
}

// ---------------- TN FP16 GEMM: cp.async 3-stage, BK=64, ldmatrix ------------
// Tile 128x128, BK=64 fp16 (four k16 steps per stage). 256 threads, 8 warps in
// a 4(m) x 2(n) grid, warp tile 32x64. Smem row = 64 fp16 = 128B data + 16B
// pad (144B stride): conflict-free ldmatrix. 2 CTAs/SM, regs = 128 (RF cap).
// kk rotation: warps 4-7 iterate k16 steps starting at kk=2 so the two
// same-CTA warps on each SMSP run LDSM and MMA bursts in anti-phase.
constexpr int BM = 128, BN = 128, BK = 64;
constexpr int STAGES  = 3;
constexpr int ROW_B   = 144;                        // bytes per smem row
constexpr int TILE_B  = 128 * ROW_B;                // 18432 B per operand tile
constexpr int STAGE_B = 2 * TILE_B;                 // 36864 B
constexpr int SMEM_B  = STAGES * STAGE_B + 1024;    // 111616 B (+ decay table)

enum { EPI_NONE = 0, EPI_DECAY = 1, EPI_RES = 2, EPI_BIAS_GELU = 3,
       EPI_BIAS_RES = 4, EPI_QKVG = 5 };

template<int EPI, bool TRILA, bool REVY>
__global__ void __launch_bounds__(256, 2)
gemm_h(const __half* __restrict__ A, const __half* __restrict__ Bm, void* __restrict__ Cv,
       int K, int lda, int ldb, int ldc,
       long long sAb, long long sAh, long long sBb, long long sBh,
       long long sCb, long long sCh, int ZD,
       const float* __restrict__ bias, const float* __restrict__ res,
       __half* __restrict__ D2, __half* __restrict__ D3, __half* __restrict__ D4)
{
    // half outputs for QKVG / DECAY / BIAS_GELU; float otherwise
    constexpr bool OUTH = (EPI == EPI_QKVG || EPI == EPI_DECAY || EPI == EPI_BIAS_GELU);
    __half* Ch = (__half*)Cv;
    float*  Cf = (float*)Cv;

    extern __shared__ float smem[];
    uint32_t sbase;
    asm("{ .reg .u64 t; cvta.to.shared.u64 t, %1; cvt.u32.u64 %0, t; }"
        : "=r"(sbase) : "l"(smem));
    float* dtab = smem + (STAGES * STAGE_B) / 4;

    int t  = threadIdx.x;
    int ln = t & 31;
    int w  = t >> 5;
    int wm = w >> 1;          // 0..3 -> m offset wm*32
    int wn = w & 1;           // 0..1 -> n offset wn*64
    int kkrot = (w >> 2) << 1;   // warps 0-3: 0, warps 4-7: 2 (anti-phase)

    int by = REVY ? ((int)gridDim.y - 1 - (int)blockIdx.y) : (int)blockIdx.y;
    int row0 = by * BM;
    int col0 = blockIdx.x * BN;
    int z = blockIdx.z;
    int hh = z % ZD;
    long long bb = z / ZD;
    A  += bb * sAb + (long long)hh * sAh;
    Bm += bb * sBb + (long long)hh * sBh;
    if (OUTH) Ch += bb * sCb + (long long)hh * sCh;
    else      Cf += bb * sCb + (long long)hh * sCh;

    // Causal: score blocks strictly above the diagonal are zero AND never read
    // by the clamped score@V GEMM (Kend = row0+BM) — skip compute AND stores.
    if (EPI == EPI_DECAY && row0 + BM <= col0) return;

    if (EPI == EPI_DECAY) {
        float gamma = 1.f - expf(-(3.46573590f + 0.396084103f * (float)hh));
        float lg = logf(gamma);
        int d = row0 - col0 - 127 + t;
        dtab[t] = (d < 0) ? 0.f : expf(lg * (float)d);
        // visibility established by the first __syncthreads in the main loop
    }

    int Kend = TRILA ? min(K, row0 + BM) : K;
    int nk = Kend / BK;

    const __half* Ap0 = A  + (size_t)row0 * lda;
    const __half* Bp0 = Bm + (size_t)col0 * ldb;
    int cRow = t >> 3, cC = t & 7;   // 16B chunk mapping: 1024 chunks / operand

    auto issue = [&](int s, int kt) {
        if (kt < nk) {
            uint32_t sa = sbase + s * STAGE_B;
            uint32_t sb = sa + TILE_B;
            #pragma unroll
            for (int i = 0; i < 4; i++) {
                int row = cRow + i * 32;
                cp16(sa + row * ROW_B + cC * 16,
                     Ap0 + (size_t)row * lda + kt * BK + cC * 8);
                cp16(sb + row * ROW_B + cC * 16,
                     Bp0 + (size_t)row * ldb + kt * BK + cC * 8);
            }
        }
        asm volatile("cp.async.commit_group;");
    };

    issue(0, 0); issue(1, 1);

    float acc[2][8][4];
    #pragma unroll
    for (int mt = 0; mt < 2; mt++)
        #pragma unroll
        for (int nt = 0; nt < 8; nt++)
            #pragma unroll
            for (int i = 0; i < 4; i++) acc[mt][nt][i] = 0.f;

    // ldmatrix per-lane address components
    int aR = wm * 32 + ((ln >> 3) & 1) * 8 + (ln & 7);
    int aH = ln >> 4;                       // k-half chunk: 0,0,1,1 per octet
    int bR = wn * 64 + ((ln >> 4) & 1) * 8 + (ln & 7);
    int bH = (ln >> 3) & 1;                 // k-half chunk: 0,1,0,1 per octet

    int cur = 0;
    for (int kt = 0; kt < nk; kt++) {
        asm volatile("cp.async.wait_group 1;");
        __syncthreads();
        int nxt = cur + 2; if (nxt >= 3) nxt -= 3;
        issue(nxt, kt + 2);

        uint32_t sa = sbase + cur * STAGE_B;
        uint32_t sb = sa + TILE_B;
        #pragma unroll
        for (int kx = 0; kx < 4; kx++) {     // four k16 steps, warp-rotated
            int kk = (kx + kkrot) & 3;
            uint32_t af[2][4];
            #pragma unroll
            for (int mt = 0; mt < 2; mt++)
                ldsm4(af[mt], sa + (aR + mt * 16) * ROW_B + kk * 32 + aH * 16);
            uint32_t bf[8][2];
            #pragma unroll
            for (int pp = 0; pp < 4; pp++) {
                uint32_t tmp[4];
                ldsm4(tmp, sb + (bR + pp * 16) * ROW_B + kk * 32 + bH * 16);
                bf[2 * pp][0]     = tmp[0];
                bf[2 * pp][1]     = tmp[1];
                bf[2 * pp + 1][0] = tmp[2];
                bf[2 * pp + 1][1] = tmp[3];
            }
            #pragma unroll
            for (int mt = 0; mt < 2; mt++)
                #pragma unroll
                for (int nt = 0; nt < 8; nt++)
                    mma_f16(acc[mt][nt], af[mt], bf[nt]);
        }
        cur++; if (cur == 3) cur = 0;
    }

    // --- epilogue ---
    int dmin = row0 - col0 - 127;
    #pragma unroll
    for (int mt = 0; mt < 2; mt++) {
        int r0 = row0 + wm * 32 + mt * 16 + (ln >> 2);
        #pragma unroll
        for (int nt = 0; nt < 8; nt++) {
            int cc = col0 + wn * 64 + nt * 8 + (ln & 3) * 2;
            #pragma unroll
            for (int half = 0; half < 2; half++) {
                int grow = r0 + half * 8;
                float v0 = acc[mt][nt][half * 2 + 0];
                float v1 = acc[mt][nt][half * 2 + 1];
                if (EPI == EPI_QKVG) {
                    // fused q/k/vT/gate routing; widx uniform per CTA (BN=128)
                    int widx = cc >> 11;
                    int lcol = cc & 2047;
                    __half h0 = __float2half_rn(v0), h1 = __float2half_rn(v1);
                    if (widx == 0) {
                        *(__half2*)&Ch[(size_t)grow * 2048 + lcol] = __halves2half2(h0, h1);
                    } else if (widx == 1) {
                        *(__half2*)&D2[(size_t)grow * 2048 + lcol] = __halves2half2(h0, h1);
                    } else if (widx == 2) {
                        // vT[b][channel][s]
                        size_t vb = ((size_t)(grow >> 10) << 21) + (size_t)(grow & 1023);
                        D3[vb + (size_t)lcol * 1024]       = h0;
                        D3[vb + (size_t)(lcol + 1) * 1024] = h1;
                    } else {
                        *(__half2*)&D4[(size_t)grow * 2048 + lcol] = __halves2half2(h0, h1);
                    }
                    continue;
                }
                if (EPI == EPI_DECAY) {
                    int d0 = grow - cc, d1 = d0 - 1;
                    v0 = (d0 < 0) ? 0.f : v0 * dtab[d0 - dmin];
                    v1 = (d1 < 0) ? 0.f : v1 * dtab[d1 - dmin];
                    *(__half2*)&Ch[(size_t)grow * ldc + cc] =
                        __halves2half2(__float2half_rn(v0), __float2half_rn(v1));
                    continue;
                }
                if (EPI == EPI_RES) {
                    v0 += res[(size_t)grow * ldc + cc];
                    v1 += res[(size_t)grow * ldc + cc + 1];
                } else if (EPI == EPI_BIAS_GELU) {
                    v0 += bias[cc];
                    v1 += bias[cc + 1];
                    float u0 = v0, u1 = v1;
                    v0 = 0.5f * u0 * (1.f + tanhf(0.7978845608f * (u0 + 0.044715f * u0 * u0 * u0)));
                    v1 = 0.5f * u1 * (1.f + tanhf(0.7978845608f * (u1 + 0.044715f * u1 * u1 * u1)));
                } else if (EPI == EPI_BIAS_RES) {
                    v0 += bias[cc]     + res[(size_t)grow * ldc + cc];
                    v1 += bias[cc + 1] + res[(size_t)grow * ldc + cc + 1];
                }
                if (EPI == EPI_BIAS_GELU) {
                    *(__half2*)&Ch[(size_t)grow * ldc + cc] =
                        __halves2half2(__float2half_rn(v0), __float2half_rn(v1));
                } else {
                    *(float2*)&Cf[(size_t)grow * ldc + cc] = make_float2(v0, v1);
                }
            }
        }
    }
}

// ---------------------------------------------------------------------------
template<int EPI, bool TRILA, bool REVY>
static void set_smem() {
    cudaFuncSetAttribute(gemm_h<EPI, TRILA, REVY>,
                         cudaFuncAttributeMaxDynamicSharedMemorySize, SMEM_B);
}

extern "C" void kernel_launch(void* const* d_in, const int* in_sizes, int n_in,
                              void* d_out, int out_size) {
    const float* x   = (const float*)d_in[0];
    const float* Wq  = (const float*)d_in[1];
    const float* Wk  = (const float*)d_in[2];
    const float* Wv  = (const float*)d_in[3];
    const float* Wg  = (const float*)d_in[4];
    const float* Wo  = (const float*)d_in[5];
    const float* gng = (const float*)d_in[6];
    const float* gnb = (const float*)d_in[7];
    const float* W1  = (const float*)d_in[8];
    const float* b1  = (const float*)d_in[9];
    const float* W2  = (const float*)d_in[10];
    const float* b2  = (const float*)d_in[11];
    const float* lng = (const float*)d_in[12];
    const float* lnb = (const float*)d_in[13];
    float* out = (float*)d_out;

    __half *xn, *q, *k, *vT, *gt, *zb, *sc, *ffn, *wt;
    float *y, *ret, *x1;
    cudaGetSymbolAddress((void**)&xn,  g_xn);
    cudaGetSymbolAddress((void**)&q,   g_q);
    cudaGetSymbolAddress((void**)&k,   g_k);
    cudaGetSymbolAddress((void**)&vT,  g_vT);
    cudaGetSymbolAddress((void**)&gt,  g_gt);
    cudaGetSymbolAddress((void**)&zb,  g_z);
    cudaGetSymbolAddress((void**)&sc,  g_sc);
    cudaGetSymbolAddress((void**)&ffn, g_ffn);
    cudaGetSymbolAddress((void**)&wt,  g_wt);
    cudaGetSymbolAddress((void**)&y,   g_y);
    cudaGetSymbolAddress((void**)&ret, g_ret);
    cudaGetSymbolAddress((void**)&x1,  g_x1);

    set_smem<EPI_QKVG,      false, false>();
    set_smem<EPI_DECAY,     false, true >();
    set_smem<EPI_NONE,      true,  true >();
    set_smem<EPI_RES,       false, false>();
    set_smem<EPI_BIAS_GELU, false, false>();
    set_smem<EPI_BIAS_RES,  false, false>();

    dim3 blk(256);

    // --- transpose + convert all weights into g_wt (2 launches) -------------
    wt_hh_k<<<dim3(Hdim / 32, Hdim / 32, LAYERS * 5), blk>>>(Wq, Wk, Wv, Wg, Wo, wt);
    wt_ffall_k<<<dim3(256, 256, LAYERS * 2), blk>>>(W1, W2, wt);

    dim3 gp(Hdim / BN, MT / BM);            // 16 x 32

    for (int i = 0; i < LAYERS; i++) {
        const float* xin = (i == 0) ? x : x1;
        __half* base = wt + (size_t)i * WT_L;

        ln_k<<<MT, blk>>>(xin, lng, lnb, xn);

        // fused q/k/vT/gate projection: one N=8192 GEMM over concatenated weights
        dim3 gqkvg((4 * Hdim) / BN, MT / BM); // 64 x 32
        gemm_h<EPI_QKVG, false, false><<<gqkvg, blk, SMEM_B>>>(xn, base, q,
            Hdim, Hdim, Hdim, Hdim, 0, 0, 0, 0, 0, 0, 1, nullptr, nullptr,
            k, vT, gt);

        // scores = (q @ k^T) * D (upper blocks skipped entirely; never read)
        dim3 gs(Sn / BN, Sn / BM, Bn * NH);   // 8 x 8 x 32
        gemm_h<EPI_DECAY, false, true><<<gs, blk, SMEM_B>>>(q, k, sc,
            HD, Hdim, Hdim, Sn,
            (long long)Sn * Hdim, (long long)HD,
            (long long)Sn * Hdim, (long long)HD,
            (long long)NH * Sn * Sn, (long long)Sn * Sn, NH, nullptr, nullptr,
            nullptr, nullptr, nullptr);

        // y = scores @ v : A=sc [S,S] fp16, B=vT [HD,S] fp16, K clamped causal
        dim3 gy(HD / BN, Sn / BM, Bn * NH);   // 2 x 8 x 32
        gemm_h<EPI_NONE, true, true><<<gy, blk, SMEM_B>>>(sc, vT, y,
            Sn, Sn, Sn, Hdim,
            (long long)NH * Sn * Sn, (long long)Sn * Sn,
            (long long)Hdim * Sn, (long long)HD * Sn,
            (long long)Sn * Hdim, (long long)HD, NH, nullptr, nullptr,
            nullptr, nullptr, nullptr);

        gn_gate_k<<<MT * NH, blk>>>(y, gt, gng + (size_t)i * Hdim,
                                    gnb + (size_t)i * Hdim, zb);

        gemm_h<EPI_RES, false, false><<<gp, blk, SMEM_B>>>(zb, base + 4 * M4, ret,
            Hdim, Hdim, Hdim, Hdim, 0, 0, 0, 0, 0, 0, 1, nullptr, xin,
            nullptr, nullptr, nullptr);

        ln_k<<<MT, blk>>>(ret, lng, lnb, xn);

        dim3 g1(FFdim / BN, MT / BM);         // 64 x 32
        gemm_h<EPI_BIAS_GELU, false, false><<<g1, blk, SMEM_B>>>(xn, base + 5 * M4,
            ffn, Hdim, Hdim, Hdim, FFdim,
            0, 0, 0, 0, 0, 0, 1, b1 + (size_t)i * FFdim, nullptr,
            nullptr, nullptr, nullptr);

        float* dst = (i == LAYERS - 1) ? out : x1;
        gemm_h<EPI_BIAS_RES, false, false><<<gp, blk, SMEM_B>>>(ffn,
            base + 5 * M4 + M16, dst, FFdim, FFdim, FFdim, Hdim,
            0, 0, 0, 0, 0, 0, 1, b2 + (size_t)i * Hdim, ret,
            nullptr, nullptr, nullptr);
    }
}

// round 17
// speedup vs baseline: 1.0075x; 1.0075x over previous
#include <cuda_runtime.h>
#include <cuda_fp16.h>
#include <math.h>
#include <stdint.h>

// ---------------------------------------------------------------------------
// RetentiveNetwork forward — FP16 mma.sync (m16n8k16) TN GEMMs, fp32 accum.
// L=2, H=2048, HEADS=8, HEAD=256, FF=8192, B=4, S=1024.
// R17 (= R16 resubmit): exact R14 GEMM (best config: 128x128, 4x2 warps,
// 2 CTA/SM, BK=64, 3-stage) + single-pass (sum, sumsq) norm reductions.
// ---------------------------------------------------------------------------

constexpr int LAYERS = 2;
constexpr int Hdim   = 2048;
constexpr int NH     = 8;
constexpr int HD     = 256;
constexpr int FFdim  = 8192;
constexpr int Bn     = 4;
constexpr int Sn     = 1024;
constexpr int MT     = Bn * Sn;

// ---------------- scratch ---------------------------------------------------
__device__ __half g_xn [MT * Hdim];
__device__ __half g_q  [MT * Hdim];
__device__ __half g_k  [MT * Hdim];
__device__ __half g_vT [MT * Hdim];     // [b][channel][s]
__device__ __half g_gt [MT * Hdim];
__device__ __half g_z  [MT * Hdim];
__device__ __half g_sc [(size_t)Bn * NH * Sn * Sn];
__device__ __half g_ffn[(size_t)MT * FFdim];
__device__ float  g_y  [MT * Hdim];
__device__ float  g_ret[MT * Hdim];
__device__ float  g_x1 [MT * Hdim];
constexpr size_t M4   = (size_t)4  * 1024 * 1024;
constexpr size_t M16  = (size_t)16 * 1024 * 1024;
constexpr size_t WT_L = (size_t)52 * 1024 * 1024;
__device__ __half g_wt[(size_t)LAYERS * WT_L];

// ---------------- helpers ---------------------------------------------------
// Single-chain reduction of (sum, sumsq) packed as float2.
__device__ __forceinline__ float2 blockReduce2(float a, float b, float2* sh) {
    int lane = threadIdx.x & 31, w = threadIdx.x >> 5;
    #pragma unroll
    for (int o = 16; o; o >>= 1) {
        a += __shfl_xor_sync(0xffffffffu, a, o);
        b += __shfl_xor_sync(0xffffffffu, b, o);
    }
    if (lane == 0) sh[w] = make_float2(a, b);
    __syncthreads();
    if (w == 0) {
        float2 r = (lane < (int)(blockDim.x >> 5)) ? sh[lane] : make_float2(0.f, 0.f);
        #pragma unroll
        for (int o = 4; o; o >>= 1) {
            r.x += __shfl_xor_sync(0xffffffffu, r.x, o);
            r.y += __shfl_xor_sync(0xffffffffu, r.y, o);
        }
        if (lane == 0) sh[0] = r;
    }
    __syncthreads();
    float2 res = sh[0];
    __syncthreads();
    return res;
}

__device__ __forceinline__ void mma_f16(float* c, const uint32_t* a, const uint32_t* b) {
    asm volatile(
        "mma.sync.aligned.m16n8k16.row.col.f32.f16.f16.f32 "
        "{%0,%1,%2,%3}, {%4,%5,%6,%7}, {%8,%9}, {%0,%1,%2,%3};"
        : "+f"(c[0]), "+f"(c[1]), "+f"(c[2]), "+f"(c[3])
        : "r"(a[0]), "r"(a[1]), "r"(a[2]), "r"(a[3]), "r"(b[0]), "r"(b[1]));
}

__device__ __forceinline__ void ldsm4(uint32_t* r, uint32_t addr) {
    asm volatile("ldmatrix.sync.aligned.m8n8.x4.shared.b16 {%0,%1,%2,%3}, [%4];"
        : "=r"(r[0]), "=r"(r[1]), "=r"(r[2]), "=r"(r[3]) : "r"(addr));
}

__device__ __forceinline__ void cp16(uint32_t dst, const void* src) {
    asm volatile("cp.async.cg.shared.global [%0], [%1], 16;" :: "r"(dst), "l"(src));
}

// ---------------- LayerNorm (float in -> fp16 out, single-pass) -------------
__global__ void ln_k(const float* __restrict__ x, const float* __restrict__ g,
                     const float* __restrict__ b, __half* __restrict__ o) {
    __shared__ float2 sh[8];
    int tok = blockIdx.x;
    const float* xp = x + (size_t)tok * Hdim;
    __half* op = o + (size_t)tok * Hdim;
    int t = threadIdx.x;
    float v[8];
    float s = 0.f, ss = 0.f;
    #pragma unroll
    for (int i = 0; i < 8; i++) {
        v[i] = xp[t + 256 * i];
        s += v[i];
        ss += v[i] * v[i];
    }
    float2 r = blockReduce2(s, ss, sh);
    float mu = r.x * (1.f / Hdim);
    float var = r.y * (1.f / Hdim) - mu * mu;
    float rs = rsqrtf(var + 1e-5f);
    #pragma unroll
    for (int i = 0; i < 8; i++) {
        int c = t + 256 * i;
        op[c] = __float2half_rn((v[i] - mu) * rs * g[c] + b[c]);
    }
}

// ---------------- GroupNorm + SiLU gate (single-pass) -----------------------
__global__ void gn_gate_k(const float* __restrict__ y, const __half* __restrict__ gate,
                          const float* __restrict__ gg, const float* __restrict__ gb,
                          __half* __restrict__ z) {
    __shared__ float2 sh[8];
    int grp = blockIdx.x;
    int h = grp & (NH - 1);
    size_t base = (size_t)(grp >> 3) * Hdim + (size_t)h * HD;
    int t = threadIdx.x;
    float val = y[base + t];
    float2 r = blockReduce2(val, val * val, sh);
    float mu = r.x * (1.f / HD);
    float var = r.y * (1.f / HD) - mu * mu;
    float rs = rsqrtf(var + 1e-5f);
    int c = h * HD + t;
    float gv = __half2float(gate[base + t]);
    float silu = gv / (1.f + expf(-gv));
    z[base + t] = __float2half_rn(((val - mu) * rs * gg[c] + gb[c]) * silu);
}

// ---------------- weight transpose + fp16 convert (2 launches) --------------
__global__ void wt_hh_k(const float* __restrict__ Wq, const float* __restrict__ Wk,
                        const float* __restrict__ Wv, const float* __restrict__ Wg,
                        const float* __restrict__ Wo, __half* __restrict__ wt) {
    __shared__ float tile[32][33];
    int z = blockIdx.z;
    int layer = z / 5, widx = z % 5;
    const float* W;
    switch (widx) {
        case 0: W = Wq; break;
        case 1: W = Wk; break;
        case 2: W = Wv; break;
        case 3: W = Wg; break;
        default: W = Wo; break;
    }
    W += (size_t)layer * Hdim * Hdim;
    __half* WT = wt + (size_t)layer * WT_L + (size_t)widx * M4;
    int tx = threadIdx.x & 31, ty = threadIdx.x >> 5;
    int k0 = blockIdx.y * 32, n0 = blockIdx.x * 32;
    #pragma unroll
    for (int j = 0; j < 32; j += 8)
        tile[ty + j][tx] = W[(size_t)(k0 + ty + j) * Hdim + n0 + tx];
    __syncthreads();
    #pragma unroll
    for (int j = 0; j < 32; j += 8)
        WT[(size_t)(n0 + ty + j) * Hdim + k0 + tx] = __float2half_rn(tile[tx][ty + j]);
}

__global__ void wt_ffall_k(const float* __restrict__ W1, const float* __restrict__ W2,
                           __half* __restrict__ wt) {
    __shared__ float tile[32][33];
    int z = blockIdx.z;
    int layer = z >> 1, which = z & 1;
    int K = which ? FFdim : Hdim;
    int N = which ? Hdim : FFdim;
    const float* Ws = which ? (W2 + (size_t)layer * FFdim * Hdim)
                            : (W1 + (size_t)layer * Hdim * FFdim);
    __half* WT = wt + (size_t)layer * WT_L + 5 * M4 + (which ? M16 : 0);
    int k0 = blockIdx.y * 32, n0 = blockIdx.x * 32;
    if (k0 >= K || n0 >= N) return;
    int tx = threadIdx.x & 31, ty = threadIdx.x >> 5;
    #pragma unroll
    for (int j = 0; j < 32; j += 8)
        tile[ty + j][tx] = Ws[(size_t)(k0 + ty + j) * N + n0 + tx];
    __syncthreads();
    #pragma unroll
    for (int j = 0; j < 32; j += 8)
        WT[(size_t)(n0 + ty + j) * K + k0 + tx] = __float2half_rn(tile[tx][ty + j]);
}

// ---------------- TN FP16 GEMM: cp.async 3-stage, BK=64, ldmatrix ------------
// Tile 128x128, BK=64 fp16 (four k16 steps per stage). 256 threads, 8 warps in
// a 4(m) x 2(n) grid, warp tile 32x64. Smem row = 64 fp16 = 128B data + 16B
// pad (144B stride): conflict-free ldmatrix. 2 CTAs/SM, regs = 128 (RF cap).
constexpr int BM = 128, BN = 128, BK = 64;
constexpr int STAGES  = 3;
constexpr int ROW_B   = 144;                        // bytes per smem row
constexpr int TILE_B  = 128 * ROW_B;                // 18432 B per operand tile
constexpr int STAGE_B = 2 * TILE_B;                 // 36864 B
constexpr int SMEM_B  = STAGES * STAGE_B + 1024;    // 111616 B (+ decay table)

enum { EPI_NONE = 0, EPI_DECAY = 1, EPI_RES = 2, EPI_BIAS_GELU = 3,
       EPI_BIAS_RES = 4, EPI_QKVG = 5 };

template<int EPI, bool TRILA, bool REVY>
__global__ void __launch_bounds__(256, 2)
gemm_h(const __half* __restrict__ A, const __half* __restrict__ Bm, void* __restrict__ Cv,
       int K, int lda, int ldb, int ldc,
       long long sAb, long long sAh, long long sBb, long long sBh,
       long long sCb, long long sCh, int ZD,
       const float* __restrict__ bias, const float* __restrict__ res,
       __half* __restrict__ D2, __half* __restrict__ D3, __half* __restrict__ D4)
{
    // half outputs for QKVG / DECAY / BIAS_GELU; float otherwise
    constexpr bool OUTH = (EPI == EPI_QKVG || EPI == EPI_DECAY || EPI == EPI_BIAS_GELU);
    __half* Ch = (__half*)Cv;
    float*  Cf = (float*)Cv;

    extern __shared__ float smem[];
    uint32_t sbase;
    asm("{ .reg .u64 t; cvta.to.shared.u64 t, %1; cvt.u32.u64 %0, t; }"
        : "=r"(sbase) : "l"(smem));
    float* dtab = smem + (STAGES * STAGE_B) / 4;

    int t  = threadIdx.x;
    int ln = t & 31;
    int w  = t >> 5;
    int wm = w >> 1;          // 0..3 -> m offset wm*32
    int wn = w & 1;           // 0..1 -> n offset wn*64

    int by = REVY ? ((int)gridDim.y - 1 - (int)blockIdx.y) : (int)blockIdx.y;
    int row0 = by * BM;
    int col0 = blockIdx.x * BN;
    int z = blockIdx.z;
    int hh = z % ZD;
    long long bb = z / ZD;
    A  += bb * sAb + (long long)hh * sAh;
    Bm += bb * sBb + (long long)hh * sBh;
    if (OUTH) Ch += bb * sCb + (long long)hh * sCh;
    else      Cf += bb * sCb + (long long)hh * sCh;

    // Causal: score blocks strictly above the diagonal are zero AND never read
    // by the clamped score@V GEMM (Kend = row0+BM) — skip compute AND stores.
    if (EPI == EPI_DECAY && row0 + BM <= col0) return;

    if (EPI == EPI_DECAY) {
        float gamma = 1.f - expf(-(3.46573590f + 0.396084103f * (float)hh));
        float lg = logf(gamma);
        int d = row0 - col0 - 127 + t;
        dtab[t] = (d < 0) ? 0.f : expf(lg * (float)d);
        // visibility established by the first __syncthreads in the main loop
    }

    int Kend = TRILA ? min(K, row0 + BM) : K;
    int nk = Kend / BK;

    const __half* Ap0 = A  + (size_t)row0 * lda;
    const __half* Bp0 = Bm + (size_t)col0 * ldb;
    int cRow = t >> 3, cC = t & 7;   // 16B chunk mapping: 1024 chunks / operand

    auto issue = [&](int s, int kt) {
        if (kt < nk) {
            uint32_t sa = sbase + s * STAGE_B;
            uint32_t sb = sa + TILE_B;
            #pragma unroll
            for (int i = 0; i < 4; i++) {
                int row = cRow + i * 32;
                cp16(sa + row * ROW_B + cC * 16,
                     Ap0 + (size_t)row * lda + kt * BK + cC * 8);
                cp16(sb + row * ROW_B + cC * 16,
                     Bp0 + (size_t)row * ldb + kt * BK + cC * 8);
            }
        }
        asm volatile("cp.async.commit_group;");
    };

    issue(0, 0); issue(1, 1);

    float acc[2][8][4];
    #pragma unroll
    for (int mt = 0; mt < 2; mt++)
        #pragma unroll
        for (int nt = 0; nt < 8; nt++)
            #pragma unroll
            for (int i = 0; i < 4; i++) acc[mt][nt][i] = 0.f;

    // ldmatrix per-lane address components
    int aR = wm * 32 + ((ln >> 3) & 1) * 8 + (ln & 7);
    int aH = ln >> 4;                       // k-half chunk: 0,0,1,1 per octet
    int bR = wn * 64 + ((ln >> 4) & 1) * 8 + (ln & 7);
    int bH = (ln >> 3) & 1;                 // k-half chunk: 0,1,0,1 per octet

    int cur = 0;
    for (int kt = 0; kt < nk; kt++) {
        asm volatile("cp.async.wait_group 1;");
        __syncthreads();
        int nxt = cur + 2; if (nxt >= 3) nxt -= 3;
        issue(nxt, kt + 2);

        uint32_t sa = sbase + cur * STAGE_B;
        uint32_t sb = sa + TILE_B;
        #pragma unroll
        for (int kk = 0; kk < 4; kk++) {     // four k16 steps
            uint32_t af[2][4];
            #pragma unroll
            for (int mt = 0; mt < 2; mt++)
                ldsm4(af[mt], sa + (aR + mt * 16) * ROW_B + kk * 32 + aH * 16);
            uint32_t bf[8][2];
            #pragma unroll
            for (int pp = 0; pp < 4; pp++) {
                uint32_t tmp[4];
                ldsm4(tmp, sb + (bR + pp * 16) * ROW_B + kk * 32 + bH * 16);
                bf[2 * pp][0]     = tmp[0];
                bf[2 * pp][1]     = tmp[1];
                bf[2 * pp + 1][0] = tmp[2];
                bf[2 * pp + 1][1] = tmp[3];
            }
            #pragma unroll
            for (int mt = 0; mt < 2; mt++)
                #pragma unroll
                for (int nt = 0; nt < 8; nt++)
                    mma_f16(acc[mt][nt], af[mt], bf[nt]);
        }
        cur++; if (cur == 3) cur = 0;
    }

    // --- epilogue ---
    int dmin = row0 - col0 - 127;
    #pragma unroll
    for (int mt = 0; mt < 2; mt++) {
        int r0 = row0 + wm * 32 + mt * 16 + (ln >> 2);
        #pragma unroll
        for (int nt = 0; nt < 8; nt++) {
            int cc = col0 + wn * 64 + nt * 8 + (ln & 3) * 2;
            #pragma unroll
            for (int half = 0; half < 2; half++) {
                int grow = r0 + half * 8;
                float v0 = acc[mt][nt][half * 2 + 0];
                float v1 = acc[mt][nt][half * 2 + 1];
                if (EPI == EPI_QKVG) {
                    // fused q/k/vT/gate routing; widx uniform per CTA (BN=128)
                    int widx = cc >> 11;
                    int lcol = cc & 2047;
                    __half h0 = __float2half_rn(v0), h1 = __float2half_rn(v1);
                    if (widx == 0) {
                        *(__half2*)&Ch[(size_t)grow * 2048 + lcol] = __halves2half2(h0, h1);
                    } else if (widx == 1) {
                        *(__half2*)&D2[(size_t)grow * 2048 + lcol] = __halves2half2(h0, h1);
                    } else if (widx == 2) {
                        // vT[b][channel][s]
                        size_t vb = ((size_t)(grow >> 10) << 21) + (size_t)(grow & 1023);
                        D3[vb + (size_t)lcol * 1024]       = h0;
                        D3[vb + (size_t)(lcol + 1) * 1024] = h1;
                    } else {
                        *(__half2*)&D4[(size_t)grow * 2048 + lcol] = __halves2half2(h0, h1);
                    }
                    continue;
                }
                if (EPI == EPI_DECAY) {
                    int d0 = grow - cc, d1 = d0 - 1;
                    v0 = (d0 < 0) ? 0.f : v0 * dtab[d0 - dmin];
                    v1 = (d1 < 0) ? 0.f : v1 * dtab[d1 - dmin];
                    *(__half2*)&Ch[(size_t)grow * ldc + cc] =
                        __halves2half2(__float2half_rn(v0), __float2half_rn(v1));
                    continue;
                }
                if (EPI == EPI_RES) {
                    v0 += res[(size_t)grow * ldc + cc];
                    v1 += res[(size_t)grow * ldc + cc + 1];
                } else if (EPI == EPI_BIAS_GELU) {
                    v0 += bias[cc];
                    v1 += bias[cc + 1];
                    float u0 = v0, u1 = v1;
                    v0 = 0.5f * u0 * (1.f + tanhf(0.7978845608f * (u0 + 0.044715f * u0 * u0 * u0)));
                    v1 = 0.5f * u1 * (1.f + tanhf(0.7978845608f * (u1 + 0.044715f * u1 * u1 * u1)));
                } else if (EPI == EPI_BIAS_RES) {
                    v0 += bias[cc]     + res[(size_t)grow * ldc + cc];
                    v1 += bias[cc + 1] + res[(size_t)grow * ldc + cc + 1];
                }
                if (EPI == EPI_BIAS_GELU) {
                    *(__half2*)&Ch[(size_t)grow * ldc + cc] =
                        __halves2half2(__float2half_rn(v0), __float2half_rn(v1));
                } else {
                    *(float2*)&Cf[(size_t)grow * ldc + cc] = make_float2(v0, v1);
                }
            }
        }
    }
}

// ---------------------------------------------------------------------------
template<int EPI, bool TRILA, bool REVY>
static void set_smem() {
    cudaFuncSetAttribute(gemm_h<EPI, TRILA, REVY>,
                         cudaFuncAttributeMaxDynamicSharedMemorySize, SMEM_B);
}

extern "C" void kernel_launch(void* const* d_in, const int* in_sizes, int n_in,
                              void* d_out, int out_size) {
    const float* x   = (const float*)d_in[0];
    const float* Wq  = (const float*)d_in[1];
    const float* Wk  = (const float*)d_in[2];
    const float* Wv  = (const float*)d_in[3];
    const float* Wg  = (const float*)d_in[4];
    const float* Wo  = (const float*)d_in[5];
    const float* gng = (const float*)d_in[6];
    const float* gnb = (const float*)d_in[7];
    const float* W1  = (const float*)d_in[8];
    const float* b1  = (const float*)d_in[9];
    const float* W2  = (const float*)d_in[10];
    const float* b2  = (const float*)d_in[11];
    const float* lng = (const float*)d_in[12];
    const float* lnb = (const float*)d_in[13];
    float* out = (float*)d_out;

    __half *xn, *q, *k, *vT, *gt, *zb, *sc, *ffn, *wt;
    float *y, *ret, *x1;
    cudaGetSymbolAddress((void**)&xn,  g_xn);
    cudaGetSymbolAddress((void**)&q,   g_q);
    cudaGetSymbolAddress((void**)&k,   g_k);
    cudaGetSymbolAddress((void**)&vT,  g_vT);
    cudaGetSymbolAddress((void**)&gt,  g_gt);
    cudaGetSymbolAddress((void**)&zb,  g_z);
    cudaGetSymbolAddress((void**)&sc,  g_sc);
    cudaGetSymbolAddress((void**)&ffn, g_ffn);
    cudaGetSymbolAddress((void**)&wt,  g_wt);
    cudaGetSymbolAddress((void**)&y,   g_y);
    cudaGetSymbolAddress((void**)&ret, g_ret);
    cudaGetSymbolAddress((void**)&x1,  g_x1);

    set_smem<EPI_QKVG,      false, false>();
    set_smem<EPI_DECAY,     false, true >();
    set_smem<EPI_NONE,      true,  true >();
    set_smem<EPI_RES,       false, false>();
    set_smem<EPI_BIAS_GELU, false, false>();
    set_smem<EPI_BIAS_RES,  false, false>();

    dim3 blk(256);

    // --- transpose + convert all weights into g_wt (2 launches) -------------
    wt_hh_k<<<dim3(Hdim / 32, Hdim / 32, LAYERS * 5), blk>>>(Wq, Wk, Wv, Wg, Wo, wt);
    wt_ffall_k<<<dim3(256, 256, LAYERS * 2), blk>>>(W1, W2, wt);

    dim3 gp(Hdim / BN, MT / BM);            // 16 x 32

    for (int i = 0; i < LAYERS; i++) {
        const float* xin = (i == 0) ? x : x1;
        __half* base = wt + (size_t)i * WT_L;

        ln_k<<<MT, blk>>>(xin, lng, lnb, xn);

        // fused q/k/vT/gate projection: one N=8192 GEMM over concatenated weights
        dim3 gqkvg((4 * Hdim) / BN, MT / BM); // 64 x 32
        gemm_h<EPI_QKVG, false, false><<<gqkvg, blk, SMEM_B>>>(xn, base, q,
            Hdim, Hdim, Hdim, Hdim, 0, 0, 0, 0, 0, 0, 1, nullptr, nullptr,
            k, vT, gt);

        // scores = (q @ k^T) * D (upper blocks skipped entirely; never read)
        dim3 gs(Sn / BN, Sn / BM, Bn * NH);   // 8 x 8 x 32
        gemm_h<EPI_DECAY, false, true><<<gs, blk, SMEM_B>>>(q, k, sc,
            HD, Hdim, Hdim, Sn,
            (long long)Sn * Hdim, (long long)HD,
            (long long)Sn * Hdim, (long long)HD,
            (long long)NH * Sn * Sn, (long long)Sn * Sn, NH, nullptr, nullptr,
            nullptr, nullptr, nullptr);

        // y = scores @ v : A=sc [S,S] fp16, B=vT [HD,S] fp16, K clamped causal
        dim3 gy(HD / BN, Sn / BM, Bn * NH);   // 2 x 8 x 32
        gemm_h<EPI_NONE, true, true><<<gy, blk, SMEM_B>>>(sc, vT, y,
            Sn, Sn, Sn, Hdim,
            (long long)NH * Sn * Sn, (long long)Sn * Sn,
            (long long)Hdim * Sn, (long long)HD * Sn,
            (long long)Sn * Hdim, (long long)HD, NH, nullptr, nullptr,
            nullptr, nullptr, nullptr);

        gn_gate_k<<<MT * NH, blk>>>(y, gt, gng + (size_t)i * Hdim,
                                    gnb + (size_t)i * Hdim, zb);

        gemm_h<EPI_RES, false, false><<<gp, blk, SMEM_B>>>(zb, base + 4 * M4, ret,
            Hdim, Hdim, Hdim, Hdim, 0, 0, 0, 0, 0, 0, 1, nullptr, xin,
            nullptr, nullptr, nullptr);

        ln_k<<<MT, blk>>>(ret, lng, lnb, xn);

        dim3 g1(FFdim / BN, MT / BM);         // 64 x 32
        gemm_h<EPI_BIAS_GELU, false, false><<<g1, blk, SMEM_B>>>(xn, base + 5 * M4,
            ffn, Hdim, Hdim, Hdim, FFdim,
            0, 0, 0, 0, 0, 0, 1, b1 + (size_t)i * FFdim, nullptr,
            nullptr, nullptr, nullptr);

        float* dst = (i == LAYERS - 1) ? out : x1;
        gemm_h<EPI_BIAS_RES, false, false><<<gp, blk, SMEM_B>>>(ffn,
            base + 5 * M4 + M16, dst, FFdim, FFdim, FFdim, Hdim,
            0, 0, 0, 0, 0, 0, 1, b2 + (size_t)i * Hdim, ret,
            nullptr, nullptr, nullptr);
    }
}